// round 3
// baseline (speedup 1.0000x reference)
#include <cuda_runtime.h>
#include <cstdint>

#define NH 8
#define NB 4
#define TT 1024
#define DM 512
#define QKVLD 1536
#define BT 4096   // NB*TT

// ---------------- device scratch (static: allocation rules) ----------------
__device__ float g_qkv[BT * QKVLD];            // 25.2 MB  [b,t, q|k|v]
__device__ float g_S[NH * NB * TT * TT];       // 134 MB   scores/probs [hb][t][s]
__device__ float g_ctx[BT * DM];               // 8 MB
__device__ float g_res[BT * DM];               // 8 MB
__device__ float g_mask[NH * DM];
__device__ float g_m2[NH * DM];
__device__ float g_invs[NH];
__device__ int   g_band[2 * NH];               // lo,hi per head (mult of 8)
__device__ int   g_anymask;

// ---------------- helpers ----------------
__device__ __forceinline__ float fast_exp(float x) {
    // x <= 0 expected (post max-subtraction); accurate to ~2.4e-6 rel
    x = fmaxf(x, -87.3f);
    float y = x * 1.4426950408889634f;
    float n = rintf(y);
    float t = (y - n) * 0.6931471805599453f;
    float p = 1.0f + t * (1.0f + t * (0.5f + t * (0.16666667f + t * (0.041666668f + t * 0.008333334f))));
    int e = (int)n;
    return p * __int_as_float((e + 127) << 23);
}

__device__ __forceinline__ float warp_max(float v) {
#pragma unroll
    for (int o = 16; o; o >>= 1) v = fmaxf(v, __shfl_xor_sync(0xffffffffu, v, o));
    return v;
}
__device__ __forceinline__ float warp_sum(float v) {
#pragma unroll
    for (int o = 16; o; o >>= 1) v += __shfl_xor_sync(0xffffffffu, v, o);
    return v;
}

// ---------------- kernel 0: setup ----------------
__global__ void k_setup(const float* __restrict__ hw, const unsigned char* __restrict__ pm) {
    __shared__ float s_start[NH], s_dim[NH];
    int tid = threadIdx.x;
    if (tid == 0) {
        g_anymask = 0;
        float g[NH];
        float mx = -1e30f;
        for (int h = 0; h < NH; h++) { g[h] = hw[h]; mx = fmaxf(mx, g[h]); }
        float sum = 0.f;
        for (int h = 0; h < NH; h++) { g[h] = expf(g[h] - mx); sum += g[h]; }
        float c = 0.f;
        for (int h = 0; h < NH; h++) {
            float gate = g[h] / sum;
            float dh = fmaxf(16.0f + gate * 384.0f, 0.0f);
            s_dim[h] = dh;
            s_start[h] = c;
            g_invs[h] = rsqrtf(dh + 1e-6f);
            int lo = (int)floorf(c) - 6; if (lo < 0) lo = 0; lo &= ~7;
            int hi = (int)ceilf(c + dh) + 6; if (hi > DM) hi = DM;
            hi = (hi + 7) & ~7; if (hi > DM) hi = DM;
            g_band[2 * h] = lo;
            g_band[2 * h + 1] = hi;
            c += dh;
        }
    }
    __syncthreads();
    // key_padding_mask: any-nonzero reduction (enables softmax fast path)
    const uint32_t* p32 = (const uint32_t*)pm;
    uint32_t v = 0;
    for (int i = tid; i < (NB * TT) / 4; i += blockDim.x) v |= p32[i];
    if (v) atomicOr(&g_anymask, 1);
    // soft masks
    for (int i = tid; i < NH * DM; i += blockDim.x) {
        int h = i >> 9, d = i & (DM - 1);
        float p = (float)d;
        float l = 1.f / (1.f + expf(-(p - s_start[h]) * 10.f));
        float r = 1.f / (1.f + expf(-((s_start[h] + s_dim[h]) - p) * 10.f));
        float m = l * r;
        g_mask[i] = m;
        g_m2[i] = m * m;
    }
}

// ---------------- 128x128x8 fp32 sgemm body (256 thr, 8x8 micro) ----------------
__device__ __forceinline__ void sgemm128_body(
    const float* __restrict__ A, int lda,
    const float* __restrict__ Bm, int ldb,
    const float* __restrict__ bias,
    const float* __restrict__ resid, int ldr,
    float* __restrict__ C, int ldc, int K)
{
    __shared__ float As[8][132];
    __shared__ float Bs[8][128];
    int tid = threadIdx.x;
    const float* Ab = A + (size_t)(blockIdx.y * 128) * lda;
    const float* Bb = Bm + blockIdx.x * 128;
    int rowA = tid >> 1, cA = (tid & 1) * 4;
    int rowB = tid >> 5, cB = (tid & 31) * 4;
    int r0 = (tid >> 4) << 3, c0 = (tid & 15) << 3;
    float acc[8][8];
#pragma unroll
    for (int i = 0; i < 8; i++)
#pragma unroll
        for (int j = 0; j < 8; j++) acc[i][j] = 0.f;

    for (int k0 = 0; k0 < K; k0 += 8) {
        float4 a4 = *(const float4*)(Ab + (size_t)rowA * lda + k0 + cA);
        As[cA + 0][rowA] = a4.x; As[cA + 1][rowA] = a4.y;
        As[cA + 2][rowA] = a4.z; As[cA + 3][rowA] = a4.w;
        float4 b4 = *(const float4*)(Bb + (size_t)(k0 + rowB) * ldb + cB);
        *(float4*)&Bs[rowB][cB] = b4;
        __syncthreads();
#pragma unroll
        for (int k = 0; k < 8; k++) {
            float a[8], b[8];
            *(float4*)(a)     = *(const float4*)&As[k][r0];
            *(float4*)(a + 4) = *(const float4*)&As[k][r0 + 4];
            *(float4*)(b)     = *(const float4*)&Bs[k][c0];
            *(float4*)(b + 4) = *(const float4*)&Bs[k][c0 + 4];
#pragma unroll
            for (int i = 0; i < 8; i++)
#pragma unroll
                for (int j = 0; j < 8; j++) acc[i][j] = fmaf(a[i], b[j], acc[i][j]);
        }
        __syncthreads();
    }
    int grow = blockIdx.y * 128 + r0;
    int gcol = blockIdx.x * 128 + c0;
#pragma unroll
    for (int i = 0; i < 8; i++) {
        int r = grow + i;
#pragma unroll
        for (int j = 0; j < 8; j += 4) {
            int c = gcol + j;
            float4 o;
            o.x = acc[i][j + 0] + bias[c + 0];
            o.y = acc[i][j + 1] + bias[c + 1];
            o.z = acc[i][j + 2] + bias[c + 2];
            o.w = acc[i][j + 3] + bias[c + 3];
            if (resid) {
                float4 rr = *(const float4*)(resid + (size_t)r * ldr + c);
                o.x += rr.x; o.y += rr.y; o.z += rr.z; o.w += rr.w;
            }
            *(float4*)(C + (size_t)r * ldc + c) = o;
        }
    }
}

__global__ __launch_bounds__(256) void k_gemm_qkv(
    const float* __restrict__ query, const float* __restrict__ Wqkv, const float* __restrict__ bqkv)
{
    sgemm128_body(query, DM, Wqkv, QKVLD, bqkv, nullptr, 0, g_qkv, QKVLD, DM);
}

__global__ __launch_bounds__(256) void k_gemm_out(
    const float* __restrict__ Wout, const float* __restrict__ bout, const float* __restrict__ query)
{
    sgemm128_body(g_ctx, DM, Wout, DM, bout, query, DM, g_res, DM, DM);
}

// ---------------- kernel: per-head banded scores S = (q*m^2) @ k^T * inv_scale --------
__global__ __launch_bounds__(64) void k_scores() {
    int hb = blockIdx.z;
    int h = hb >> 2, b = hb & 3;
    int lo = g_band[2 * h], hi = g_band[2 * h + 1];
    int t0 = blockIdx.y * 64, s0 = blockIdx.x * 64;
    const float* base = g_qkv + (size_t)b * TT * QKVLD;
    const float* m2p = g_m2 + h * DM;

    __shared__ float As[8][68];
    __shared__ float Bs[8][68];
    int tid = threadIdx.x;
    int lrow = tid >> 1, lc = (tid & 1) * 4;
    int r0 = (tid >> 3) << 3, c0 = (tid & 7) << 3;
    float acc[8][8];
#pragma unroll
    for (int i = 0; i < 8; i++)
#pragma unroll
        for (int j = 0; j < 8; j++) acc[i][j] = 0.f;

    for (int k0 = lo; k0 < hi; k0 += 8) {
        float4 mv = *(const float4*)(m2p + k0 + lc);
#pragma unroll
        for (int g = 0; g < 2; g++) {
            int rr = lrow + g * 32;
            float4 qa = *(const float4*)(base + (size_t)(t0 + rr) * QKVLD + k0 + lc);
            As[lc + 0][rr] = qa.x * mv.x; As[lc + 1][rr] = qa.y * mv.y;
            As[lc + 2][rr] = qa.z * mv.z; As[lc + 3][rr] = qa.w * mv.w;
            float4 ka = *(const float4*)(base + (size_t)(s0 + rr) * QKVLD + 512 + k0 + lc);
            Bs[lc + 0][rr] = ka.x; Bs[lc + 1][rr] = ka.y;
            Bs[lc + 2][rr] = ka.z; Bs[lc + 3][rr] = ka.w;
        }
        __syncthreads();
#pragma unroll
        for (int k = 0; k < 8; k++) {
            float a[8], b2[8];
            *(float4*)(a)      = *(const float4*)&As[k][r0];
            *(float4*)(a + 4)  = *(const float4*)&As[k][r0 + 4];
            *(float4*)(b2)     = *(const float4*)&Bs[k][c0];
            *(float4*)(b2 + 4) = *(const float4*)&Bs[k][c0 + 4];
#pragma unroll
            for (int i = 0; i < 8; i++)
#pragma unroll
                for (int j = 0; j < 8; j++) acc[i][j] = fmaf(a[i], b2[j], acc[i][j]);
        }
        __syncthreads();
    }
    float sc = g_invs[h];
    float* Sp = g_S + ((size_t)hb * TT + t0) * TT + s0;
#pragma unroll
    for (int i = 0; i < 8; i++) {
#pragma unroll
        for (int j = 0; j < 8; j += 4) {
            float4 o;
            o.x = acc[i][j + 0] * sc; o.y = acc[i][j + 1] * sc;
            o.z = acc[i][j + 2] * sc; o.w = acc[i][j + 3] * sc;
            *(float4*)(Sp + (size_t)(r0 + i) * TT + c0 + j) = o;
        }
    }
}

// ---------------- kernel: row softmax (one warp / row), polynomial exp --------
__global__ __launch_bounds__(256) void k_softmax(const unsigned char* __restrict__ pm) {
    int warp = threadIdx.x >> 5, lane = threadIdx.x & 31;
    int row = blockIdx.x * 8 + warp;         // 32768 rows
    int b = (row >> 10) & 3;
    float* Sp = g_S + (size_t)row * TT;
    int any = g_anymask;

    float v[32];
    float mx = -3.0e38f;
    if (any) {
        const unsigned char* pb = pm + b * TT;
#pragma unroll
        for (int i = 0; i < 32; i++) {
            int s = lane + i * 32;
            float x = Sp[s];
            if (pb[s]) x = -1.0e9f;
            v[i] = x; mx = fmaxf(mx, x);
        }
    } else {
#pragma unroll
        for (int i = 0; i < 32; i++) {
            float x = Sp[lane + i * 32];
            v[i] = x; mx = fmaxf(mx, x);
        }
    }
    mx = warp_max(mx);
    float sum = 0.f;
#pragma unroll
    for (int i = 0; i < 32; i++) { float e = fast_exp(v[i] - mx); v[i] = e; sum += e; }
    sum = warp_sum(sum);
    float inv = 1.f / sum;
#pragma unroll
    for (int i = 0; i < 32; i++) Sp[lane + i * 32] = v[i] * inv;
}

// ---------------- kernel: ctx tile [64t x 64d] = sum over intersecting heads P @ (v*m) ---
__global__ __launch_bounds__(64) void k_ctx() {
    int b = blockIdx.z;
    int t0 = blockIdx.y * 64;
    int d0 = blockIdx.x * 64;
    __shared__ float Ps[16][68];
    __shared__ float Vs[16][68];
    int tid = threadIdx.x;
    int r0 = (tid >> 3) << 3, c0 = (tid & 7) << 3;
    int pr = tid >> 2, pc = (tid & 3) * 4;
    int vr = tid >> 2, vc = (tid & 3) * 16;
    const float* vbase = g_qkv + (size_t)b * TT * QKVLD + 1024;

    float acc[8][8];
#pragma unroll
    for (int i = 0; i < 8; i++)
#pragma unroll
        for (int j = 0; j < 8; j++) acc[i][j] = 0.f;

    for (int h = 0; h < NH; h++) {
        int lo = g_band[2 * h], hi = g_band[2 * h + 1];
        if (hi <= d0 || lo >= d0 + 64) continue;
        const float* Pb = g_S + ((size_t)(h * NB + b) * TT + t0) * TT;
        const float* mp = g_mask + h * DM + d0;
        float4 mm[4];
#pragma unroll
        for (int q = 0; q < 4; q++) mm[q] = *(const float4*)(mp + vc + q * 4);

        for (int k0 = 0; k0 < TT; k0 += 16) {
#pragma unroll
            for (int g = 0; g < 4; g++) {
                int rr = pr + g * 16;
                float4 pv = *(const float4*)(Pb + (size_t)rr * TT + k0 + pc);
                Ps[pc + 0][rr] = pv.x; Ps[pc + 1][rr] = pv.y;
                Ps[pc + 2][rr] = pv.z; Ps[pc + 3][rr] = pv.w;
            }
#pragma unroll
            for (int q = 0; q < 4; q++) {
                float4 vv = *(const float4*)(vbase + (size_t)(k0 + vr) * QKVLD + d0 + vc + q * 4);
                float4 o;
                o.x = vv.x * mm[q].x; o.y = vv.y * mm[q].y;
                o.z = vv.z * mm[q].z; o.w = vv.w * mm[q].w;
                *(float4*)&Vs[vr][vc + q * 4] = o;
            }
            __syncthreads();
#pragma unroll
            for (int k = 0; k < 16; k++) {
                float a[8], b2[8];
                *(float4*)(a)      = *(const float4*)&Ps[k][r0];
                *(float4*)(a + 4)  = *(const float4*)&Ps[k][r0 + 4];
                *(float4*)(b2)     = *(const float4*)&Vs[k][c0];
                *(float4*)(b2 + 4) = *(const float4*)&Vs[k][c0 + 4];
#pragma unroll
                for (int i = 0; i < 8; i++)
#pragma unroll
                    for (int j = 0; j < 8; j++) acc[i][j] = fmaf(a[i], b2[j], acc[i][j]);
            }
            __syncthreads();
        }
    }
#pragma unroll
    for (int i = 0; i < 8; i++) {
        size_t r = (size_t)(b * TT + t0 + r0 + i);
#pragma unroll
        for (int j = 0; j < 8; j += 4) {
            float4 o;
            o.x = acc[i][j + 0]; o.y = acc[i][j + 1];
            o.z = acc[i][j + 2]; o.w = acc[i][j + 3];
            *(float4*)(g_ctx + r * DM + d0 + c0 + j) = o;
        }
    }
}

// ---------------- kernel: layernorm -> output ----------------
__global__ __launch_bounds__(128) void k_ln(
    const float* __restrict__ gamma, const float* __restrict__ beta, float* __restrict__ out)
{
    int row = blockIdx.x, tid = threadIdx.x;
    const float* rp = g_res + (size_t)row * DM;
    float4 x = *(const float4*)(rp + tid * 4);
    float s  = x.x + x.y + x.z + x.w;
    float ss = fmaf(x.x, x.x, fmaf(x.y, x.y, fmaf(x.z, x.z, x.w * x.w)));
    s = warp_sum(s);
    ss = warp_sum(ss);
    __shared__ float sb[8];
    int w = tid >> 5, l = tid & 31;
    if (l == 0) { sb[w] = s; sb[4 + w] = ss; }
    __syncthreads();
    s  = sb[0] + sb[1] + sb[2] + sb[3];
    ss = sb[4] + sb[5] + sb[6] + sb[7];
    float mu = s * (1.0f / DM);
    float var = ss * (1.0f / DM) - mu * mu;
    float rs = rsqrtf(var + 1e-5f);
    float4 gm = *(const float4*)(gamma + tid * 4);
    float4 bt = *(const float4*)(beta + tid * 4);
    float4 o;
    o.x = (x.x - mu) * rs * gm.x + bt.x;
    o.y = (x.y - mu) * rs * gm.y + bt.y;
    o.z = (x.z - mu) * rs * gm.z + bt.z;
    o.w = (x.w - mu) * rs * gm.w + bt.w;
    *(float4*)(out + (size_t)row * DM + tid * 4) = o;
}

// ---------------- launch ----------------
extern "C" void kernel_launch(void* const* d_in, const int* in_sizes, int n_in,
                              void* d_out, int out_size) {
    const float* query = (const float*)d_in[0];
    const float* hw    = (const float*)d_in[1];
    const float* Wqkv  = (const float*)d_in[2];
    const float* bqkv  = (const float*)d_in[3];
    const float* Wout  = (const float*)d_in[4];
    const float* bout  = (const float*)d_in[5];
    const float* gamma = (const float*)d_in[6];
    const float* beta  = (const float*)d_in[7];
    const unsigned char* pm = (const unsigned char*)d_in[8];
    float* out = (float*)d_out;

    k_setup<<<1, 512>>>(hw, pm);
    k_gemm_qkv<<<dim3(QKVLD / 128, BT / 128), 256>>>(query, Wqkv, bqkv);
    k_scores<<<dim3(TT / 64, TT / 64, NH * NB), 64>>>();
    k_softmax<<<(NH * NB * TT) / 8, 256>>>(pm);
    k_ctx<<<dim3(DM / 64, TT / 64, NB), 64>>>();
    k_gemm_out<<<dim3(DM / 128, BT / 128), 256>>>(Wout, bout, query);
    k_ln<<<BT, 128>>>(gamma, beta, out);
}

// round 8
// speedup vs baseline: 1.0016x; 1.0016x over previous
#include <cuda_runtime.h>
#include <cstdint>

#define NH 8
#define NB 4
#define TT 1024
#define DM 512
#define QKVLD 1536
#define BT 4096   // NB*TT

// ---------------- device scratch (static: allocation rules) ----------------
__device__ float g_qkv[BT * QKVLD];            // 25.2 MB  [b,t, q|k|v]
__device__ float g_S[NH * NB * TT * TT];       // 134 MB   scores/probs [hb][t][s]
__device__ float g_ctx[BT * DM];               // 8 MB
__device__ float g_res[BT * DM];               // 8 MB
__device__ float g_mask[NH * DM];
__device__ float g_m2[NH * DM];
__device__ float g_invs[NH];
__device__ int   g_band[2 * NH];               // lo,hi per head (mult of 8)
__device__ int   g_anymask;

// ---------------- helpers ----------------
__device__ __forceinline__ float fast_exp(float x) {
    // x <= 0 expected (post max-subtraction); accurate to ~2.4e-6 rel
    x = fmaxf(x, -87.3f);
    float y = x * 1.4426950408889634f;
    float n = rintf(y);
    float t = (y - n) * 0.6931471805599453f;
    float p = 1.0f + t * (1.0f + t * (0.5f + t * (0.16666667f + t * (0.041666668f + t * 0.008333334f))));
    int e = (int)n;
    return p * __int_as_float((e + 127) << 23);
}

__device__ __forceinline__ float warp_max(float v) {
#pragma unroll
    for (int o = 16; o; o >>= 1) v = fmaxf(v, __shfl_xor_sync(0xffffffffu, v, o));
    return v;
}
__device__ __forceinline__ float warp_sum(float v) {
#pragma unroll
    for (int o = 16; o; o >>= 1) v += __shfl_xor_sync(0xffffffffu, v, o);
    return v;
}

// ---------------- kernel 0: setup ----------------
__global__ void k_setup(const float* __restrict__ hw, const unsigned char* __restrict__ pm) {
    __shared__ float s_start[NH], s_dim[NH];
    int tid = threadIdx.x;
    if (tid == 0) {
        g_anymask = 0;
        float g[NH];
        float mx = -1e30f;
        for (int h = 0; h < NH; h++) { g[h] = hw[h]; mx = fmaxf(mx, g[h]); }
        float sum = 0.f;
        for (int h = 0; h < NH; h++) { g[h] = expf(g[h] - mx); sum += g[h]; }
        float c = 0.f;
        for (int h = 0; h < NH; h++) {
            float gate = g[h] / sum;
            float dh = fmaxf(16.0f + gate * 384.0f, 0.0f);
            s_dim[h] = dh;
            s_start[h] = c;
            g_invs[h] = rsqrtf(dh + 1e-6f);
            int lo = (int)floorf(c) - 6; if (lo < 0) lo = 0; lo &= ~7;
            int hi = (int)ceilf(c + dh) + 6; if (hi > DM) hi = DM;
            hi = (hi + 7) & ~7; if (hi > DM) hi = DM;
            g_band[2 * h] = lo;
            g_band[2 * h + 1] = hi;
            c += dh;
        }
    }
    __syncthreads();
    // key_padding_mask: any-nonzero reduction (enables softmax fast path)
    const uint32_t* p32 = (const uint32_t*)pm;
    uint32_t v = 0;
    for (int i = tid; i < (NB * TT) / 4; i += blockDim.x) v |= p32[i];
    if (v) atomicOr(&g_anymask, 1);
    // soft masks
    for (int i = tid; i < NH * DM; i += blockDim.x) {
        int h = i >> 9, d = i & (DM - 1);
        float p = (float)d;
        float l = 1.f / (1.f + expf(-(p - s_start[h]) * 10.f));
        float r = 1.f / (1.f + expf(-((s_start[h] + s_dim[h]) - p) * 10.f));
        float m = l * r;
        g_mask[i] = m;
        g_m2[i] = m * m;
    }
}

// ---------------- 128x128x8 fp32 sgemm body (256 thr, 8x8 micro) ----------------
__device__ __forceinline__ void sgemm128_body(
    const float* __restrict__ A, int lda,
    const float* __restrict__ Bm, int ldb,
    const float* __restrict__ bias,
    const float* __restrict__ resid, int ldr,
    float* __restrict__ C, int ldc, int K)
{
    __shared__ float As[8][132];
    __shared__ float Bs[8][128];
    int tid = threadIdx.x;
    const float* Ab = A + (size_t)(blockIdx.y * 128) * lda;
    const float* Bb = Bm + blockIdx.x * 128;
    int rowA = tid >> 1, cA = (tid & 1) * 4;
    int rowB = tid >> 5, cB = (tid & 31) * 4;
    int r0 = (tid >> 4) << 3, c0 = (tid & 15) << 3;
    float acc[8][8];
#pragma unroll
    for (int i = 0; i < 8; i++)
#pragma unroll
        for (int j = 0; j < 8; j++) acc[i][j] = 0.f;

    for (int k0 = 0; k0 < K; k0 += 8) {
        float4 a4 = *(const float4*)(Ab + (size_t)rowA * lda + k0 + cA);
        As[cA + 0][rowA] = a4.x; As[cA + 1][rowA] = a4.y;
        As[cA + 2][rowA] = a4.z; As[cA + 3][rowA] = a4.w;
        float4 b4 = *(const float4*)(Bb + (size_t)(k0 + rowB) * ldb + cB);
        *(float4*)&Bs[rowB][cB] = b4;
        __syncthreads();
#pragma unroll
        for (int k = 0; k < 8; k++) {
            float a[8], b[8];
            *(float4*)(a)     = *(const float4*)&As[k][r0];
            *(float4*)(a + 4) = *(const float4*)&As[k][r0 + 4];
            *(float4*)(b)     = *(const float4*)&Bs[k][c0];
            *(float4*)(b + 4) = *(const float4*)&Bs[k][c0 + 4];
#pragma unroll
            for (int i = 0; i < 8; i++)
#pragma unroll
                for (int j = 0; j < 8; j++) acc[i][j] = fmaf(a[i], b[j], acc[i][j]);
        }
        __syncthreads();
    }
    int grow = blockIdx.y * 128 + r0;
    int gcol = blockIdx.x * 128 + c0;
#pragma unroll
    for (int i = 0; i < 8; i++) {
        int r = grow + i;
#pragma unroll
        for (int j = 0; j < 8; j += 4) {
            int c = gcol + j;
            float4 o;
            o.x = acc[i][j + 0] + bias[c + 0];
            o.y = acc[i][j + 1] + bias[c + 1];
            o.z = acc[i][j + 2] + bias[c + 2];
            o.w = acc[i][j + 3] + bias[c + 3];
            if (resid) {
                float4 rr = *(const float4*)(resid + (size_t)r * ldr + c);
                o.x += rr.x; o.y += rr.y; o.z += rr.z; o.w += rr.w;
            }
            *(float4*)(C + (size_t)r * ldc + c) = o;
        }
    }
}

__global__ __launch_bounds__(256) void k_gemm_qkv(
    const float* __restrict__ query, const float* __restrict__ Wqkv, const float* __restrict__ bqkv)
{
    sgemm128_body(query, DM, Wqkv, QKVLD, bqkv, nullptr, 0, g_qkv, QKVLD, DM);
}

__global__ __launch_bounds__(256) void k_gemm_out(
    const float* __restrict__ Wout, const float* __restrict__ bout, const float* __restrict__ query)
{
    sgemm128_body(g_ctx, DM, Wout, DM, bout, query, DM, g_res, DM, DM);
}

// ---------------- kernel: per-head banded scores S = (q*m^2) @ k^T * inv_scale --------
__global__ __launch_bounds__(64) void k_scores() {
    int hb = blockIdx.z;
    int h = hb >> 2, b = hb & 3;
    int lo = g_band[2 * h], hi = g_band[2 * h + 1];
    int t0 = blockIdx.y * 64, s0 = blockIdx.x * 64;
    const float* base = g_qkv + (size_t)b * TT * QKVLD;
    const float* m2p = g_m2 + h * DM;

    __shared__ float As[8][68];
    __shared__ float Bs[8][68];
    int tid = threadIdx.x;
    int lrow = tid >> 1, lc = (tid & 1) * 4;
    int r0 = (tid >> 3) << 3, c0 = (tid & 7) << 3;
    float acc[8][8];
#pragma unroll
    for (int i = 0; i < 8; i++)
#pragma unroll
        for (int j = 0; j < 8; j++) acc[i][j] = 0.f;

    for (int k0 = lo; k0 < hi; k0 += 8) {
        float4 mv = *(const float4*)(m2p + k0 + lc);
#pragma unroll
        for (int g = 0; g < 2; g++) {
            int rr = lrow + g * 32;
            float4 qa = *(const float4*)(base + (size_t)(t0 + rr) * QKVLD + k0 + lc);
            As[lc + 0][rr] = qa.x * mv.x; As[lc + 1][rr] = qa.y * mv.y;
            As[lc + 2][rr] = qa.z * mv.z; As[lc + 3][rr] = qa.w * mv.w;
            float4 ka = *(const float4*)(base + (size_t)(s0 + rr) * QKVLD + 512 + k0 + lc);
            Bs[lc + 0][rr] = ka.x; Bs[lc + 1][rr] = ka.y;
            Bs[lc + 2][rr] = ka.z; Bs[lc + 3][rr] = ka.w;
        }
        __syncthreads();
#pragma unroll
        for (int k = 0; k < 8; k++) {
            float a[8], b2[8];
            *(float4*)(a)      = *(const float4*)&As[k][r0];
            *(float4*)(a + 4)  = *(const float4*)&As[k][r0 + 4];
            *(float4*)(b2)     = *(const float4*)&Bs[k][c0];
            *(float4*)(b2 + 4) = *(const float4*)&Bs[k][c0 + 4];
#pragma unroll
            for (int i = 0; i < 8; i++)
#pragma unroll
                for (int j = 0; j < 8; j++) acc[i][j] = fmaf(a[i], b2[j], acc[i][j]);
        }
        __syncthreads();
    }
    float sc = g_invs[h];
    float* Sp = g_S + ((size_t)hb * TT + t0) * TT + s0;
#pragma unroll
    for (int i = 0; i < 8; i++) {
#pragma unroll
        for (int j = 0; j < 8; j += 4) {
            float4 o;
            o.x = acc[i][j + 0] * sc; o.y = acc[i][j + 1] * sc;
            o.z = acc[i][j + 2] * sc; o.w = acc[i][j + 3] * sc;
            *(float4*)(Sp + (size_t)(r0 + i) * TT + c0 + j) = o;
        }
    }
}

// ---------------- kernel: row softmax (one warp / row), polynomial exp --------
__global__ __launch_bounds__(256) void k_softmax(const unsigned char* __restrict__ pm) {
    int warp = threadIdx.x >> 5, lane = threadIdx.x & 31;
    int row = blockIdx.x * 8 + warp;         // 32768 rows
    int b = (row >> 10) & 3;
    float* Sp = g_S + (size_t)row * TT;
    int any = g_anymask;

    float v[32];
    float mx = -3.0e38f;
    if (any) {
        const unsigned char* pb = pm + b * TT;
#pragma unroll
        for (int i = 0; i < 32; i++) {
            int s = lane + i * 32;
            float x = Sp[s];
            if (pb[s]) x = -1.0e9f;
            v[i] = x; mx = fmaxf(mx, x);
        }
    } else {
#pragma unroll
        for (int i = 0; i < 32; i++) {
            float x = Sp[lane + i * 32];
            v[i] = x; mx = fmaxf(mx, x);
        }
    }
    mx = warp_max(mx);
    float sum = 0.f;
#pragma unroll
    for (int i = 0; i < 32; i++) { float e = fast_exp(v[i] - mx); v[i] = e; sum += e; }
    sum = warp_sum(sum);
    float inv = 1.f / sum;
#pragma unroll
    for (int i = 0; i < 32; i++) Sp[lane + i * 32] = v[i] * inv;
}

// ---------------- kernel: ctx tile [64t x 64d] = sum over intersecting heads P @ (v*m) ---
__global__ __launch_bounds__(64) void k_ctx() {
    int b = blockIdx.z;
    int t0 = blockIdx.y * 64;
    int d0 = blockIdx.x * 64;
    __shared__ float Ps[16][68];
    __shared__ float Vs[16][68];
    int tid = threadIdx.x;
    int r0 = (tid >> 3) << 3, c0 = (tid & 7) << 3;
    int pr = tid >> 2, pc = (tid & 3) * 4;
    int vr = tid >> 2, vc = (tid & 3) * 16;
    const float* vbase = g_qkv + (size_t)b * TT * QKVLD + 1024;

    float acc[8][8];
#pragma unroll
    for (int i = 0; i < 8; i++)
#pragma unroll
        for (int j = 0; j < 8; j++) acc[i][j] = 0.f;

    for (int h = 0; h < NH; h++) {
        int lo = g_band[2 * h], hi = g_band[2 * h + 1];
        if (hi <= d0 || lo >= d0 + 64) continue;
        const float* Pb = g_S + ((size_t)(h * NB + b) * TT + t0) * TT;
        const float* mp = g_mask + h * DM + d0;
        float4 mm[4];
#pragma unroll
        for (int q = 0; q < 4; q++) mm[q] = *(const float4*)(mp + vc + q * 4);

        for (int k0 = 0; k0 < TT; k0 += 16) {
#pragma unroll
            for (int g = 0; g < 4; g++) {
                int rr = pr + g * 16;
                float4 pv = *(const float4*)(Pb + (size_t)rr * TT + k0 + pc);
                Ps[pc + 0][rr] = pv.x; Ps[pc + 1][rr] = pv.y;
                Ps[pc + 2][rr] = pv.z; Ps[pc + 3][rr] = pv.w;
            }
#pragma unroll
            for (int q = 0; q < 4; q++) {
                float4 vv = *(const float4*)(vbase + (size_t)(k0 + vr) * QKVLD + d0 + vc + q * 4);
                float4 o;
                o.x = vv.x * mm[q].x; o.y = vv.y * mm[q].y;
                o.z = vv.z * mm[q].z; o.w = vv.w * mm[q].w;
                *(float4*)&Vs[vr][vc + q * 4] = o;
            }
            __syncthreads();
#pragma unroll
            for (int k = 0; k < 16; k++) {
                float a[8], b2[8];
                *(float4*)(a)      = *(const float4*)&Ps[k][r0];
                *(float4*)(a + 4)  = *(const float4*)&Ps[k][r0 + 4];
                *(float4*)(b2)     = *(const float4*)&Vs[k][c0];
                *(float4*)(b2 + 4) = *(const float4*)&Vs[k][c0 + 4];
#pragma unroll
                for (int i = 0; i < 8; i++)
#pragma unroll
                    for (int j = 0; j < 8; j++) acc[i][j] = fmaf(a[i], b2[j], acc[i][j]);
            }
            __syncthreads();
        }
    }
#pragma unroll
    for (int i = 0; i < 8; i++) {
        size_t r = (size_t)(b * TT + t0 + r0 + i);
#pragma unroll
        for (int j = 0; j < 8; j += 4) {
            float4 o;
            o.x = acc[i][j + 0]; o.y = acc[i][j + 1];
            o.z = acc[i][j + 2]; o.w = acc[i][j + 3];
            *(float4*)(g_ctx + r * DM + d0 + c0 + j) = o;
        }
    }
}

// ---------------- kernel: layernorm -> output ----------------
__global__ __launch_bounds__(128) void k_ln(
    const float* __restrict__ gamma, const float* __restrict__ beta, float* __restrict__ out)
{
    int row = blockIdx.x, tid = threadIdx.x;
    const float* rp = g_res + (size_t)row * DM;
    float4 x = *(const float4*)(rp + tid * 4);
    float s  = x.x + x.y + x.z + x.w;
    float ss = fmaf(x.x, x.x, fmaf(x.y, x.y, fmaf(x.z, x.z, x.w * x.w)));
    s = warp_sum(s);
    ss = warp_sum(ss);
    __shared__ float sb[8];
    int w = tid >> 5, l = tid & 31;
    if (l == 0) { sb[w] = s; sb[4 + w] = ss; }
    __syncthreads();
    s  = sb[0] + sb[1] + sb[2] + sb[3];
    ss = sb[4] + sb[5] + sb[6] + sb[7];
    float mu = s * (1.0f / DM);
    float var = ss * (1.0f / DM) - mu * mu;
    float rs = rsqrtf(var + 1e-5f);
    float4 gm = *(const float4*)(gamma + tid * 4);
    float4 bt = *(const float4*)(beta + tid * 4);
    float4 o;
    o.x = (x.x - mu) * rs * gm.x + bt.x;
    o.y = (x.y - mu) * rs * gm.y + bt.y;
    o.z = (x.z - mu) * rs * gm.z + bt.z;
    o.w = (x.w - mu) * rs * gm.w + bt.w;
    *(float4*)(out + (size_t)row * DM + tid * 4) = o;
}

// ---------------- launch ----------------
extern "C" void kernel_launch(void* const* d_in, const int* in_sizes, int n_in,
                              void* d_out, int out_size) {
    const float* query = (const float*)d_in[0];
    const float* hw    = (const float*)d_in[1];
    const float* Wqkv  = (const float*)d_in[2];
    const float* bqkv  = (const float*)d_in[3];
    const float* Wout  = (const float*)d_in[4];
    const float* bout  = (const float*)d_in[5];
    const float* gamma = (const float*)d_in[6];
    const float* beta  = (const float*)d_in[7];
    const unsigned char* pm = (const unsigned char*)d_in[8];
    float* out = (float*)d_out;

    k_setup<<<1, 512>>>(hw, pm);
    k_gemm_qkv<<<dim3(QKVLD / 128, BT / 128), 256>>>(query, Wqkv, bqkv);
    k_scores<<<dim3(TT / 64, TT / 64, NH * NB), 64>>>();
    k_softmax<<<(NH * NB * TT) / 8, 256>>>(pm);
    k_ctx<<<dim3(DM / 64, TT / 64, NB), 64>>>();
    k_gemm_out<<<dim3(DM / 128, BT / 128), 256>>>(Wout, bout, query);
    k_ln<<<BT, 128>>>(gamma, beta, out);
}